// round 2
// baseline (speedup 1.0000x reference)
#include <cuda_runtime.h>
#include <math.h>

#define HH 100
#define WW 100
#define NN 10000
#define TAB_W 199
#define TAB_SIZE (TAB_W * TAB_W)

#define NSLICE 7
#define OCHUNK 20
#define OPB 512          // outputs per block (== threads per block in k_main)
#define MAXROWS 107      // max tab rows any block needs (100 + max i1 span 6, +1 pad)
#define STAB_PAD ((MAXROWS * TAB_W + 3) & ~3)   // 21296: 16B-align the list region
#define SLIST_MAX 1440   // >= ceil(10000/7) = 1429

__device__ float g_tab[TAB_SIZE];          // tab[a*199+b] = sqrt((a-99)^2 + (b-99)^2)
__device__ float g_A[NN];                  // A[di*100 + j1] = sum_j2 sqrt(di^2 + (j1-j2)^2)
__device__ int   g_list[NN];               // compacted py entries as encoded (i2+99)*199 + (j2+99)
__device__ int   g_nlist;
__device__ float g_pT[NSLICE * 10240];     // per-slice partial of D@py
__device__ float g_pS[NSLICE * 10240];     // per-slice partial of rowsum S

// ---------------------------------------------------------------------------
// K1: block 0 does deterministic compaction of py set-pixels (ballot scan),
//     blocks 1..39 fill the 199x199 distance table.
// ---------------------------------------------------------------------------
__global__ void k_prep(const float* __restrict__ gt) {
    if (blockIdx.x == 0) {
        __shared__ int swtot[32];
        __shared__ int swoff[32];
        __shared__ int sbase;
        int tid = threadIdx.x;
        int warp = tid >> 5, lane = tid & 31;
        if (tid == 0) sbase = 0;
        __syncthreads();
        for (int r = 0; r < 10; ++r) {
            int o = r * 1024 + tid;
            bool p = (o < NN) && (gt[o] >= 0.5f);
            unsigned bal = __ballot_sync(0xffffffffu, p);
            int pre = __popc(bal & ((1u << lane) - 1u));
            if (lane == 0) swtot[warp] = __popc(bal);
            __syncthreads();
            if (tid == 0) {
                int run = sbase;
                #pragma unroll
                for (int w = 0; w < 32; ++w) { swoff[w] = run; run += swtot[w]; }
                sbase = run;
            }
            __syncthreads();
            if (p) {
                int pos = swoff[warp] + pre;
                int i2 = o / 100, j2 = o - i2 * 100;
                g_list[pos] = (i2 + 99) * TAB_W + (j2 + 99);
            }
            __syncthreads();   // protect swtot/swoff/sbase for next round
        }
        if (tid == 0) g_nlist = sbase;
    } else {
        int idx = (blockIdx.x - 1) * 1024 + threadIdx.x;
        if (idx < TAB_SIZE) {
            int a = idx / TAB_W;
            int b = idx - a * TAB_W;
            float dx = (float)(a - 99), dy = (float)(b - 99);
            g_tab[idx] = sqrtf(dx * dx + dy * dy);
        }
    }
}

// ---------------------------------------------------------------------------
// K2: A[di][j1] = sum over j2 of tab[di+99][j2 - j1 + 99]; one block per di.
// ---------------------------------------------------------------------------
__global__ void k_A() {
    __shared__ float row[TAB_W];
    int di = blockIdx.x;
    for (int k = threadIdx.x; k < TAB_W; k += blockDim.x)
        row[k] = g_tab[(di + 99) * TAB_W + k];
    __syncthreads();
    int j1 = threadIdx.x;
    if (j1 < 100) {
        float s = 0.f;
        int base = 99 - j1;
        #pragma unroll 4
        for (int j2 = 0; j2 < 100; ++j2) s += row[base + j2];
        g_A[di * 100 + j1] = s;
    }
}

// ---------------------------------------------------------------------------
// K3: main. grid = OCHUNK * NSLICE = 140 blocks, 512 threads.
//   block (chunk, s): outputs [chunk*512, chunk*512+512), list slice s of NSLICE.
//   Stages only the needed ~106 tab rows + its list slice into shared.
//   Also computes a slice of the (input-independent) rowsum S.
// ---------------------------------------------------------------------------
__global__ __launch_bounds__(OPB, 1) void k_main() {
    extern __shared__ float sm[];
    float* stab = sm;
    int* slist = (int*)(sm + STAB_PAD);      // 16B-aligned

    int chunk = blockIdx.x / NSLICE;
    int s = blockIdx.x - chunk * NSLICE;
    int o0 = chunk * OPB;
    int i1lo = o0 / 100;
    int i1hi = (o0 + OPB - 1) / 100; if (i1hi > 99) i1hi = 99;
    int rlo = 99 - i1hi;
    int nrows = 100 + (i1hi - i1lo);
    int radj = rlo * TAB_W;
    int tid = threadIdx.x;

    int tot = nrows * TAB_W;
    for (int k = tid; k < tot; k += OPB) stab[k] = g_tab[radj + k];

    int n = g_nlist;
    int e0 = (s * n) / NSLICE;
    int e1 = ((s + 1) * n) / NSLICE;
    int cnt = e1 - e0;
    for (int k = tid; k < cnt; k += OPB) slist[k] = g_list[e0 + k] - radj;
    __syncthreads();

    int o = o0 + tid;
    int oc = (o < NN) ? o : (NN - 1);
    int i1 = oc / 100;
    int j1 = oc - i1 * 100;
    int m = i1 * TAB_W + j1;

    float a0 = 0.f, a1 = 0.f, a2 = 0.f, a3 = 0.f;
    int k = 0;
    int n4 = cnt & ~3;
    for (; k < n4; k += 4) {
        int4 e = *(const int4*)(slist + k);   // LDS.128, warp-uniform broadcast
        a0 += stab[e.x - m];
        a1 += stab[e.y - m];
        a2 += stab[e.z - m];
        a3 += stab[e.w - m];
    }
    for (; k < cnt; ++k) a0 += stab[slist[k] - m];
    float acc = (a0 + a1) + (a2 + a3);

    // partial rowsum S over i2 in this slice's range
    int i2a = (100 * s) / NSLICE;
    int i2b = (100 * (s + 1)) / NSLICE;
    float sv = 0.f;
    for (int i2 = i2a; i2 < i2b; ++i2) {
        int di = i1 - i2; if (di < 0) di = -di;
        sv += g_A[di * 100 + j1];
    }

    if (o < NN) {
        g_pT[s * 10240 + o] = acc;
        g_pS[s * 10240 + o] = sv;
    }
}

// ---------------------------------------------------------------------------
// K4: final reduce. loss = sum_o |px[o]*S[o] - T[o]| / N^2. Single block,
//     fixed summation order => deterministic.
// ---------------------------------------------------------------------------
__global__ void k_final(const float* __restrict__ prob, float* __restrict__ out) {
    __shared__ float warpsum[32];
    int tid = threadIdx.x;
    float ls = 0.f;
    for (int o = tid; o < NN; o += 1024) {
        float T = 0.f, S = 0.f;
        #pragma unroll
        for (int s = 0; s < NSLICE; ++s) {
            T += g_pT[s * 10240 + o];
            S += g_pS[s * 10240 + o];
        }
        float px = (prob[o] >= 0.5f) ? 1.0f : 0.0f;
        ls += fabsf(px * S - T);
    }
    #pragma unroll
    for (int off = 16; off; off >>= 1) ls += __shfl_down_sync(0xffffffffu, ls, off);
    if ((tid & 31) == 0) warpsum[tid >> 5] = ls;
    __syncthreads();
    if (tid == 0) {
        float t = 0.f;
        #pragma unroll
        for (int w = 0; w < 32; ++w) t += warpsum[w];
        out[0] = t * (1.0f / ((float)NN * (float)NN));
    }
}

extern "C" void kernel_launch(void* const* d_in, const int* in_sizes, int n_in,
                              void* d_out, int out_size) {
    const float* prob = (const float*)d_in[0];
    const float* gt   = (const float*)d_in[1];
    float* out = (float*)d_out;

    size_t smem = (size_t)(STAB_PAD + SLIST_MAX) * sizeof(float);
    cudaFuncSetAttribute(k_main, cudaFuncAttributeMaxDynamicSharedMemorySize, (int)smem);

    k_prep<<<40, 1024>>>(gt);
    k_A<<<100, 128>>>();
    k_main<<<OCHUNK * NSLICE, OPB, smem>>>();
    k_final<<<1, 1024>>>(prob, out);
}

// round 3
// speedup vs baseline: 1.1313x; 1.1313x over previous
#include <cuda_runtime.h>
#include <math.h>

#define HH 100
#define WW 100
#define NN 10000
#define TAB_W 199
#define TAB_SIZE (TAB_W * TAB_W)

#define NSLICE 7
#define OCHUNK 20
#define OPB 512          // outputs per block (== threads per block in k_main)
#define MAXROWS 107      // max tab rows any block needs
#define STAB_PAD ((MAXROWS * TAB_W + 3) & ~3)   // 16B-align the list region
#define SLIST_MAX 1440   // >= ceil(10000/7)

#define RED_BLOCKS 20

__device__ float g_tab[TAB_SIZE];          // tab[a*199+b] = sqrt((a-99)^2 + (b-99)^2)
__device__ float g_A[NN];                  // A[di*100 + j1] = sum_j2 sqrt(di^2 + (j1-j2)^2)
__device__ int   g_list[NN];               // compacted py entries: (i2+99)*199 + (j2+99)
__device__ int   g_nlist;
__device__ float g_pT[NSLICE * 10240];     // per-slice partial of D@py
__device__ float g_pS[NSLICE * 10240];     // per-slice partial of rowsum S
__device__ float g_red[RED_BLOCKS];
__device__ int   g_ctr;

// ---------------------------------------------------------------------------
// K1: block 0: deterministic compaction of py set-pixels (prefetched ballot
//     scan) + counter reset. Blocks 1..39: fill 199x199 distance table.
//     Blocks 40..139: compute A analytically (no dependence on g_tab).
// ---------------------------------------------------------------------------
__global__ void k_prep(const float* __restrict__ gt) {
    int bid = blockIdx.x;
    int tid = threadIdx.x;
    if (bid == 0) {
        __shared__ int swtot[32];
        __shared__ int swoff[32];
        __shared__ int sbase;
        int warp = tid >> 5, lane = tid & 31;
        if (tid == 0) { sbase = 0; g_ctr = 0; }
        // prefetch all 10 values per thread (MLP=10, one DRAM round-trip)
        float v[10];
        #pragma unroll
        for (int r = 0; r < 10; ++r) {
            int o = r * 1024 + tid;
            v[r] = (o < NN) ? gt[o] : 0.0f;
        }
        __syncthreads();
        #pragma unroll
        for (int r = 0; r < 10; ++r) {
            int o = r * 1024 + tid;
            bool p = (o < NN) && (v[r] >= 0.5f);
            unsigned bal = __ballot_sync(0xffffffffu, p);
            int pre = __popc(bal & ((1u << lane) - 1u));
            if (lane == 0) swtot[warp] = __popc(bal);
            __syncthreads();
            if (tid == 0) {
                int run = sbase;
                #pragma unroll
                for (int w = 0; w < 32; ++w) { swoff[w] = run; run += swtot[w]; }
                sbase = run;
            }
            __syncthreads();
            if (p) {
                int pos = swoff[warp] + pre;
                int i2 = o / 100, j2 = o - i2 * 100;
                g_list[pos] = (i2 + 99) * TAB_W + (j2 + 99);
            }
            __syncthreads();
        }
        if (tid == 0) g_nlist = sbase;
    } else if (bid < 40) {
        int idx = (bid - 1) * 1024 + tid;
        if (idx < TAB_SIZE) {
            int a = idx / TAB_W;
            int b = idx - a * TAB_W;
            float dx = (float)(a - 99), dy = (float)(b - 99);
            g_tab[idx] = sqrtf(dx * dx + dy * dy);
        }
    } else {
        int di = bid - 40;           // 0..99
        int j1 = tid;
        if (j1 < 100) {
            float fd2 = (float)(di * di);
            float s = 0.f;
            #pragma unroll 4
            for (int j2 = 0; j2 < 100; ++j2) {
                float dj = (float)(j1 - j2);
                s += sqrtf(fd2 + dj * dj);
            }
            g_A[di * 100 + j1] = s;
        }
    }
}

// ---------------------------------------------------------------------------
// K2: main. grid = OCHUNK * NSLICE = 140 blocks, 512 threads.
//   block (chunk, s): outputs [chunk*512, +512), list slice s of NSLICE.
//   Stages the needed ~106 tab rows + list slice into shared. Also computes
//   a slice of the (input-independent) rowsum S.
// ---------------------------------------------------------------------------
__global__ __launch_bounds__(OPB, 1) void k_main() {
    extern __shared__ float sm[];
    float* stab = sm;
    int* slist = (int*)(sm + STAB_PAD);      // 16B-aligned

    int chunk = blockIdx.x / NSLICE;
    int s = blockIdx.x - chunk * NSLICE;
    int o0 = chunk * OPB;
    int i1lo = o0 / 100;
    int i1hi = (o0 + OPB - 1) / 100; if (i1hi > 99) i1hi = 99;
    int rlo = 99 - i1hi;
    int nrows = 100 + (i1hi - i1lo);
    int radj = rlo * TAB_W;
    int tid = threadIdx.x;

    int tot = nrows * TAB_W;
    for (int k = tid; k < tot; k += OPB) stab[k] = g_tab[radj + k];

    int n = g_nlist;
    int e0 = (s * n) / NSLICE;
    int e1 = ((s + 1) * n) / NSLICE;
    int cnt = e1 - e0;
    for (int k = tid; k < cnt; k += OPB) slist[k] = g_list[e0 + k] - radj;
    __syncthreads();

    int o = o0 + tid;
    int oc = (o < NN) ? o : (NN - 1);
    int i1 = oc / 100;
    int j1 = oc - i1 * 100;
    int m = i1 * TAB_W + j1;

    float a0 = 0.f, a1 = 0.f, a2 = 0.f, a3 = 0.f;
    int k = 0;
    int n4 = cnt & ~3;
    for (; k < n4; k += 4) {
        int4 e = *(const int4*)(slist + k);   // LDS.128, warp-uniform broadcast
        a0 += stab[e.x - m];
        a1 += stab[e.y - m];
        a2 += stab[e.z - m];
        a3 += stab[e.w - m];
    }
    for (; k < cnt; ++k) a0 += stab[slist[k] - m];
    float acc = (a0 + a1) + (a2 + a3);

    // partial rowsum S over this slice's i2 range
    int i2a = (100 * s) / NSLICE;
    int i2b = (100 * (s + 1)) / NSLICE;
    float sv = 0.f;
    for (int i2 = i2a; i2 < i2b; ++i2) {
        int di = i1 - i2; if (di < 0) di = -di;
        sv += g_A[di * 100 + j1];
    }

    if (o < NN) {
        g_pT[s * 10240 + o] = acc;
        g_pS[s * 10240 + o] = sv;
    }
}

// ---------------------------------------------------------------------------
// K3: parallel final reduce. 20 blocks x 512 threads. Each block combines
//   slice partials for 512 outputs, reduces in fixed order, writes g_red[b].
//   The last-arriving block sums the 20 partials in fixed index order and
//   writes the scalar (deterministic: summation order is index-fixed).
// ---------------------------------------------------------------------------
__global__ void k_red(const float* __restrict__ prob, float* __restrict__ out) {
    __shared__ float warpsum[16];
    __shared__ bool isLast;
    int bid = blockIdx.x;
    int tid = threadIdx.x;
    int o = bid * 512 + tid;

    float ls = 0.f;
    if (o < NN) {
        float T = 0.f, S = 0.f;
        #pragma unroll
        for (int s = 0; s < NSLICE; ++s) {
            T += g_pT[s * 10240 + o];
            S += g_pS[s * 10240 + o];
        }
        float px = (prob[o] >= 0.5f) ? 1.0f : 0.0f;
        ls = fabsf(px * S - T);
    }
    #pragma unroll
    for (int off = 16; off; off >>= 1) ls += __shfl_down_sync(0xffffffffu, ls, off);
    if ((tid & 31) == 0) warpsum[tid >> 5] = ls;
    __syncthreads();
    if (tid == 0) {
        float t = 0.f;
        #pragma unroll
        for (int w = 0; w < 16; ++w) t += warpsum[w];
        g_red[bid] = t;
        __threadfence();
        int old = atomicAdd(&g_ctr, 1);
        isLast = (old == RED_BLOCKS - 1);
    }
    __syncthreads();
    if (isLast && tid == 0) {
        float t = 0.f;
        #pragma unroll
        for (int b = 0; b < RED_BLOCKS; ++b) t += g_red[b];
        out[0] = t * (1.0f / ((float)NN * (float)NN));
    }
}

extern "C" void kernel_launch(void* const* d_in, const int* in_sizes, int n_in,
                              void* d_out, int out_size) {
    const float* prob = (const float*)d_in[0];
    const float* gt   = (const float*)d_in[1];
    float* out = (float*)d_out;

    size_t smem = (size_t)(STAB_PAD + SLIST_MAX) * sizeof(float);
    cudaFuncSetAttribute(k_main, cudaFuncAttributeMaxDynamicSharedMemorySize, (int)smem);

    k_prep<<<140, 1024>>>(gt);
    k_main<<<OCHUNK * NSLICE, OPB, smem>>>();
    k_red<<<RED_BLOCKS, 512>>>(prob, out);
}

// round 4
// speedup vs baseline: 1.1442x; 1.0114x over previous
#include <cuda_runtime.h>
#include <math.h>

#define NN 10000
#define TAB_W 199
#define NSLICE 7
#define OCHUNK 20
#define NB (OCHUNK * NSLICE)      // 140 blocks, all co-resident (<=148 SMs)
#define NT 512
#define MAXROWS 107
#define STAB_PAD ((MAXROWS * TAB_W + 3) & ~3)
#define SLIST_MAX 1440
#define NSEG 313                  // ceil(10000/32)
#define CPB 100                   // block doing compaction

__device__ float g_A[NN];                  // A[di*100+j1] = sum_j2 sqrt(di^2+(j1-j2)^2)
__device__ int   g_list[NN];               // compacted py entries: (i2+99)*199+(j2+99)
__device__ int   g_nlist;
__device__ float g_pT[NSLICE * 10240];
__device__ float g_pS[NSLICE * 10240];
__device__ float g_red[OCHUNK];
__device__ int   g_barA = 0, g_barB = 0, g_ctr2 = 0, g_done = 0;

__device__ __forceinline__ void grid_barrier(int* ctr) {
    __syncthreads();
    if (threadIdx.x == 0) {
        atomicAdd(ctr, 1);
        while (*(volatile int*)ctr != NB) __nanosleep(32);
    }
    __syncthreads();
}

__global__ __launch_bounds__(NT, 1) void k_fused(const float* __restrict__ prob,
                                                 const float* __restrict__ gt,
                                                 float* __restrict__ out) {
    extern __shared__ float sm[];
    float* stab = sm;
    int* slist = (int*)(sm + STAB_PAD);      // 16B-aligned

    const int bid = blockIdx.x;
    const int tid = threadIdx.x;
    const int warp = tid >> 5, lane = tid & 31;

    const int chunk = bid / NSLICE;
    const int s = bid - chunk * NSLICE;
    const int o0 = chunk * NT;
    const int i1lo = o0 / 100;
    int i1hi = (o0 + NT - 1) / 100; if (i1hi > 99) i1hi = 99;
    const int rlo = 99 - i1hi;
    const int nrows = 100 + (i1hi - i1lo);
    const int radj = rlo * TAB_W;

    // ---------------- Phase A ----------------
    if (bid == CPB) {
        // deterministic parallel compaction of py = (gt >= 0.5)
        __shared__ unsigned sbal[320];
        __shared__ int soff[320];
        __shared__ int stot;
        #pragma unroll
        for (int it = 0; it < 20; ++it) {
            int seg = it * 16 + warp;
            if (seg < NSEG) {
                int o = seg * 32 + lane;
                bool p = (o < NN) && (gt[o] >= 0.5f);
                unsigned bal = __ballot_sync(0xffffffffu, p);
                if (lane == 0) sbal[seg] = bal;
            }
        }
        __syncthreads();
        if (warp == 0) {                     // scan 313 counts in element order
            int base = 0;
            #pragma unroll
            for (int c = 0; c < 10; ++c) {
                int sg = c * 32 + lane;
                int cnt = (sg < NSEG) ? __popc(sbal[sg]) : 0;
                int incl = cnt;
                #pragma unroll
                for (int d = 1; d < 32; d <<= 1) {
                    int v = __shfl_up_sync(0xffffffffu, incl, d);
                    if (lane >= d) incl += v;
                }
                if (sg < NSEG) soff[sg] = base + incl - cnt;
                int tot = __shfl_sync(0xffffffffu, incl, 31);
                base += tot;
            }
            if (lane == 0) { g_nlist = base; stot = base; }
        }
        __syncthreads();
        #pragma unroll
        for (int it = 0; it < 20; ++it) {
            int seg = it * 16 + warp;
            if (seg < NSEG) {
                unsigned bal = sbal[seg];
                if ((bal >> lane) & 1u) {
                    int o = seg * 32 + lane;
                    int pre = __popc(bal & ((1u << lane) - 1u));
                    int i2 = o / 100, j2 = o - i2 * 100;
                    g_list[soff[seg] + pre] = (i2 + 99) * TAB_W + (j2 + 99);
                }
            }
        }
        (void)stot;
    } else if (bid < 100) {
        // one A-row per block: A[bid][j1]
        int j1 = tid;
        if (j1 < 100) {
            float fd2 = (float)(bid * bid);
            float a = 0.f;
            #pragma unroll 4
            for (int j2 = 0; j2 < 100; ++j2) {
                float dj = (float)(j1 - j2);
                a += sqrtf(fd2 + dj * dj);
            }
            g_A[bid * 100 + j1] = a;
        }
    }

    // every block: its stab window, computed analytically
    {
        int tot = nrows * TAB_W;
        for (int k = tid; k < tot; k += NT) {
            int a = k / TAB_W;
            int b = k - a * TAB_W;
            float dx = (float)(a + rlo - 99), dy = (float)(b - 99);
            stab[k] = sqrtf(dx * dx + dy * dy);
        }
    }

    if (bid <= CPB) __threadfence();         // publish g_A / g_list before barrier
    grid_barrier(&g_barA);

    // ---------------- Phase B: main ----------------
    int n = *(volatile int*)&g_nlist;
    int e0 = (s * n) / NSLICE;
    int e1 = ((s + 1) * n) / NSLICE;
    int cnt = e1 - e0;
    for (int k = tid; k < cnt; k += NT)
        slist[k] = (g_list[e0 + k] - radj) * 4;     // byte offsets
    __syncthreads();

    int o = o0 + tid;
    int oc = (o < NN) ? o : (NN - 1);
    int i1 = oc / 100;
    int j1 = oc - i1 * 100;
    int m = i1 * TAB_W + j1;

    unsigned stab_u32;
    asm("{ .reg .u64 t; cvta.to.shared.u64 t, %1; cvt.u32.u64 %0, t; }"
        : "=r"(stab_u32) : "l"(stab));
    unsigned tb = stab_u32 - 4u * (unsigned)m;      // pre-biased smem base

    float a0 = 0.f, a1 = 0.f, a2 = 0.f, a3 = 0.f;
    int k = 0;
    int n8 = cnt & ~7;
    for (; k < n8; k += 8) {
        int4 ea = *(const int4*)(slist + k);
        int4 eb = *(const int4*)(slist + k + 4);
        float v0, v1, v2, v3, v4, v5, v6, v7;
        asm("ld.shared.f32 %0, [%1];" : "=f"(v0) : "r"(tb + (unsigned)ea.x));
        asm("ld.shared.f32 %0, [%1];" : "=f"(v1) : "r"(tb + (unsigned)ea.y));
        asm("ld.shared.f32 %0, [%1];" : "=f"(v2) : "r"(tb + (unsigned)ea.z));
        asm("ld.shared.f32 %0, [%1];" : "=f"(v3) : "r"(tb + (unsigned)ea.w));
        asm("ld.shared.f32 %0, [%1];" : "=f"(v4) : "r"(tb + (unsigned)eb.x));
        asm("ld.shared.f32 %0, [%1];" : "=f"(v5) : "r"(tb + (unsigned)eb.y));
        asm("ld.shared.f32 %0, [%1];" : "=f"(v6) : "r"(tb + (unsigned)eb.z));
        asm("ld.shared.f32 %0, [%1];" : "=f"(v7) : "r"(tb + (unsigned)eb.w));
        a0 += v0; a1 += v1; a2 += v2; a3 += v3;
        a0 += v4; a1 += v5; a2 += v6; a3 += v7;
    }
    for (; k < cnt; ++k) {
        float v;
        asm("ld.shared.f32 %0, [%1];" : "=f"(v) : "r"(tb + (unsigned)slist[k]));
        a0 += v;
    }
    float acc = (a0 + a1) + (a2 + a3);

    // slice partial of the (input-independent) rowsum S
    int i2a = (100 * s) / NSLICE;
    int i2b = (100 * (s + 1)) / NSLICE;
    float sv = 0.f;
    for (int i2 = i2a; i2 < i2b; ++i2) {
        int di = i1 - i2; if (di < 0) di = -di;
        sv += g_A[di * 100 + j1];
    }

    if (o < NN) {
        g_pT[s * 10240 + o] = acc;
        g_pS[s * 10240 + o] = sv;
    }
    __threadfence();
    grid_barrier(&g_barB);

    // ---------------- Phase C: reduce (blocks with s == 0) ----------------
    if (s == 0) {
        __shared__ float warpsum[16];
        int oo = chunk * NT + tid;
        float ls = 0.f;
        if (oo < NN) {
            float T = 0.f, S = 0.f;
            #pragma unroll
            for (int q = 0; q < NSLICE; ++q) {
                T += g_pT[q * 10240 + oo];
                S += g_pS[q * 10240 + oo];
            }
            float px = (prob[oo] >= 0.5f) ? 1.0f : 0.0f;
            ls = fabsf(px * S - T);
        }
        #pragma unroll
        for (int off = 16; off; off >>= 1) ls += __shfl_down_sync(0xffffffffu, ls, off);
        if (lane == 0) warpsum[warp] = ls;
        __syncthreads();
        if (tid == 0) {
            float t = 0.f;
            #pragma unroll
            for (int w = 0; w < 16; ++w) t += warpsum[w];
            g_red[chunk] = t;
            __threadfence();
            int old = atomicAdd(&g_ctr2, 1);
            if (old == OCHUNK - 1) {
                float tt = 0.f;
                #pragma unroll
                for (int b = 0; b < OCHUNK; ++b) tt += g_red[b];
                out[0] = tt * (1.0f / ((float)NN * (float)NN));
            }
        }
        __syncthreads();
    }

    // ---------------- replay-safe counter reset ----------------
    __syncthreads();
    if (tid == 0) {
        int fin = atomicAdd(&g_done, 1);
        if (fin == NB - 1) {          // last block: everyone else fully done
            g_barA = 0; g_barB = 0; g_ctr2 = 0; g_done = 0;
            __threadfence();
        }
    }
}

extern "C" void kernel_launch(void* const* d_in, const int* in_sizes, int n_in,
                              void* d_out, int out_size) {
    const float* prob = (const float*)d_in[0];
    const float* gt   = (const float*)d_in[1];
    float* out = (float*)d_out;

    size_t smem = (size_t)(STAB_PAD + SLIST_MAX) * sizeof(float);
    cudaFuncSetAttribute(k_fused, cudaFuncAttributeMaxDynamicSharedMemorySize, (int)smem);
    k_fused<<<NB, NT, smem>>>(prob, gt, out);
}

// round 5
// speedup vs baseline: 1.3927x; 1.2172x over previous
#include <cuda_runtime.h>
#include <math.h>

#define NN 10000
#define NSLICE 14
#define NCHUNK 10
#define NB 140                 // all co-resident (<=148 SMs)
#define NT 512
#define OUTB 1024              // outputs per chunk (2 per thread)
#define MAXR 110               // max table rows any block needs
#define TW2 200                // u16 row width (even)
#define AWORDS (MAXR * 100)    // u32 words per table copy = 11000
#define DB (AWORDS * 4)        // byte offset of copy B = 44000
#define SLIST_OFF (2 * DB)     // 88000, 16B aligned
#define SLIST_MAX 720
#define SMEM_BYTES (SLIST_OFF + SLIST_MAX * 4)
#define NSEG 313
#define CPB 100                // compaction block (no A-row duty)
#define QSCALE 448.0f

__device__ float g_A[NN];                // A[di*100+j1] = sum_j2 sqrt(di^2+(j1-j2)^2)
__device__ int   g_list[NN];             // (i2+99)*200 + (j2+99)
__device__ int   g_nlist;
__device__ float g_pT[NSLICE * 10240];
__device__ float g_pS[NSLICE * 10240];
__device__ float g_red[NCHUNK];
__device__ int   g_barA = 0, g_barB = 0, g_ctr2 = 0, g_done = 0;

__device__ __forceinline__ void grid_barrier(int* ctr) {
    __syncthreads();
    if (threadIdx.x == 0) {
        atomicAdd(ctr, 1);
        while (*(volatile int*)ctr != NB) __nanosleep(32);
    }
    __syncthreads();
}

__device__ __forceinline__ float sqrt_fast(float x) {
    float r; asm("sqrt.approx.f32 %0, %1;" : "=f"(r) : "f"(x)); return r;
}

__global__ __launch_bounds__(NT, 1) void k_fused(const float* __restrict__ prob,
                                                 const float* __restrict__ gt,
                                                 float* __restrict__ out) {
    extern __shared__ unsigned char smraw[];
    unsigned* wA = (unsigned*)smraw;                 // u16-pair words, copy A
    unsigned* wB = (unsigned*)(smraw + DB);          // shifted copy B
    int* slist = (int*)(smraw + SLIST_OFF);

    const int bid = blockIdx.x;
    const int tid = threadIdx.x;
    const int warp = tid >> 5, lane = tid & 31;

    const int chunk = bid / NSLICE;
    const int s = bid - chunk * NSLICE;
    const int o0 = chunk * OUTB;
    const int i1lo = o0 / 100;
    int i1hi = (o0 + OUTB - 1) / 100; if (i1hi > 99) i1hi = 99;
    const int rlo = 99 - i1hi;
    const int nrows = 100 + (i1hi - i1lo);
    const int nW = nrows * 100;                      // u32 words per copy

    // ---------------- Phase A ----------------
    if (bid == CPB) {
        // deterministic parallel compaction of py = (gt >= 0.5)
        __shared__ unsigned sbal[320];
        __shared__ int soff[320];
        #pragma unroll
        for (int it = 0; it < 20; ++it) {
            int seg = it * 16 + warp;
            if (seg < NSEG) {
                int o = seg * 32 + lane;
                bool p = (o < NN) && (gt[o] >= 0.5f);
                unsigned bal = __ballot_sync(0xffffffffu, p);
                if (lane == 0) sbal[seg] = bal;
            }
        }
        __syncthreads();
        if (warp == 0) {
            int base = 0;
            #pragma unroll
            for (int c = 0; c < 10; ++c) {
                int sg = c * 32 + lane;
                int cnt = (sg < NSEG) ? __popc(sbal[sg]) : 0;
                int incl = cnt;
                #pragma unroll
                for (int d = 1; d < 32; d <<= 1) {
                    int v = __shfl_up_sync(0xffffffffu, incl, d);
                    if (lane >= d) incl += v;
                }
                if (sg < NSEG) soff[sg] = base + incl - cnt;
                base += __shfl_sync(0xffffffffu, incl, 31);
            }
            if (lane == 0) g_nlist = base;
        }
        __syncthreads();
        #pragma unroll
        for (int it = 0; it < 20; ++it) {
            int seg = it * 16 + warp;
            if (seg < NSEG) {
                unsigned bal = sbal[seg];
                if ((bal >> lane) & 1u) {
                    int o = seg * 32 + lane;
                    int pre = __popc(bal & ((1u << lane) - 1u));
                    int i2 = o / 100, j2 = o - i2 * 100;
                    g_list[soff[seg] + pre] = (i2 + 99) * TW2 + (j2 + 99);
                }
            }
        }
    } else if (bid < 100) {
        // one A-row per block (full fp32 precision)
        int j1 = tid;
        if (j1 < 100) {
            float fd2 = (float)(bid * bid);
            float a = 0.f;
            #pragma unroll 4
            for (int j2 = 0; j2 < 100; ++j2) {
                float dj = (float)(j1 - j2);
                a += sqrtf(fd2 + dj * dj);
            }
            g_A[bid * 100 + j1] = a;
        }
    }

    // all blocks: copy A of quantized table (u16 pairs)
    for (int w = tid; w < nW; w += NT) {
        int r = w / 100;
        int cw = w - r * 100;
        int dx = r + rlo - 99;
        int c0 = 2 * cw - 99;            // dy of even col
        int d2a = dx * dx + c0 * c0;
        int d2b = dx * dx + (c0 + 1) * (c0 + 1);
        unsigned ua = __float2uint_rn(sqrt_fast((float)d2a) * QSCALE);
        unsigned ub = __float2uint_rn(sqrt_fast((float)d2b) * QSCALE);
        wA[w] = ua | (ub << 16);
    }
    __syncthreads();
    // copy B: B[k] = A[k+1]  (one-u16 shift, built from copy A)
    for (int w = tid; w < nW; w += NT) {
        unsigned a = wA[w];
        unsigned b = wA[(w + 1 < nW) ? (w + 1) : w];
        wB[w] = __byte_perm(a, b, 0x5432);
    }
    __threadfence();
    grid_barrier(&g_barA);

    // ---------------- Phase B: main sparse accumulate ----------------
    int n = *(volatile int*)&g_nlist;
    int e0 = (s * n) / NSLICE;
    int e1 = ((s + 1) * n) / NSLICE;
    int cnt = e1 - e0;
    int badj = rlo * TW2 + 1;            // F = G - badj
    for (int k = tid; k < cnt; k += NT) {
        int F = g_list[e0 + k] - badj;
        int p = F & 1;
        slist[k] = 2 * (F - p) + p * DB;
    }
    __syncthreads();

    int oe = o0 + 2 * tid;               // even output; pair (oe, oe+1)
    bool valid = (oe < NN);
    int oc = valid ? oe : (NN - 2);
    int i1 = oc / 100;
    int j1 = oc - i1 * 100;              // even
    int qq = j1 >> 1;

    unsigned baseA;
    asm("{ .reg .u64 t; cvta.to.shared.u64 t, %1; cvt.u32.u64 %0, t; }"
        : "=r"(baseA) : "l"(smraw));
    unsigned tb = baseA - 400u * (unsigned)i1 - 4u * (unsigned)qq;

    unsigned aE0 = 0, aE1 = 0, aO0 = 0, aO1 = 0;
    int k = 0;
    int n8 = cnt & ~7;
    for (; k < n8; k += 8) {
        int4 ea = *(const int4*)(slist + k);
        int4 eb = *(const int4*)(slist + k + 4);
        unsigned w0, w1, w2, w3, w4, w5, w6, w7;
        asm("ld.shared.u32 %0,[%1];" : "=r"(w0) : "r"(tb + (unsigned)ea.x));
        asm("ld.shared.u32 %0,[%1];" : "=r"(w1) : "r"(tb + (unsigned)ea.y));
        asm("ld.shared.u32 %0,[%1];" : "=r"(w2) : "r"(tb + (unsigned)ea.z));
        asm("ld.shared.u32 %0,[%1];" : "=r"(w3) : "r"(tb + (unsigned)ea.w));
        asm("ld.shared.u32 %0,[%1];" : "=r"(w4) : "r"(tb + (unsigned)eb.x));
        asm("ld.shared.u32 %0,[%1];" : "=r"(w5) : "r"(tb + (unsigned)eb.y));
        asm("ld.shared.u32 %0,[%1];" : "=r"(w6) : "r"(tb + (unsigned)eb.z));
        asm("ld.shared.u32 %0,[%1];" : "=r"(w7) : "r"(tb + (unsigned)eb.w));
        aE0 = __dp2a_lo(w0, 0x0100u, aE0); aO0 = __dp2a_lo(w0, 0x0001u, aO0);
        aE1 = __dp2a_lo(w1, 0x0100u, aE1); aO1 = __dp2a_lo(w1, 0x0001u, aO1);
        aE0 = __dp2a_lo(w2, 0x0100u, aE0); aO0 = __dp2a_lo(w2, 0x0001u, aO0);
        aE1 = __dp2a_lo(w3, 0x0100u, aE1); aO1 = __dp2a_lo(w3, 0x0001u, aO1);
        aE0 = __dp2a_lo(w4, 0x0100u, aE0); aO0 = __dp2a_lo(w4, 0x0001u, aO0);
        aE1 = __dp2a_lo(w5, 0x0100u, aE1); aO1 = __dp2a_lo(w5, 0x0001u, aO1);
        aE0 = __dp2a_lo(w6, 0x0100u, aE0); aO0 = __dp2a_lo(w6, 0x0001u, aO0);
        aE1 = __dp2a_lo(w7, 0x0100u, aE1); aO1 = __dp2a_lo(w7, 0x0001u, aO1);
    }
    for (; k < cnt; ++k) {
        unsigned w0;
        asm("ld.shared.u32 %0,[%1];" : "=r"(w0) : "r"(tb + (unsigned)slist[k]));
        aE0 = __dp2a_lo(w0, 0x0100u, aE0);
        aO0 = __dp2a_lo(w0, 0x0001u, aO0);
    }
    float Te = __uint2float_rn(aE0 + aE1) * (1.0f / QSCALE);
    float To = __uint2float_rn(aO0 + aO1) * (1.0f / QSCALE);

    // slice partial of the (input-independent) rowsum S for both outputs
    int i2a = (100 * s) / NSLICE;
    int i2b = (100 * (s + 1)) / NSLICE;
    float sve = 0.f, svo = 0.f;
    const float2* A2 = (const float2*)g_A;
    for (int i2 = i2a; i2 < i2b; ++i2) {
        int di = i1 - i2; if (di < 0) di = -di;
        float2 v = A2[di * 50 + qq];
        sve += v.x; svo += v.y;
    }

    if (valid) {
        *(float2*)&g_pT[s * 10240 + oe] = make_float2(Te, To);
        *(float2*)&g_pS[s * 10240 + oe] = make_float2(sve, svo);
    }
    __threadfence();
    grid_barrier(&g_barB);

    // ---------------- Phase C: reduce (blocks with s == 0) ----------------
    if (s == 0) {
        __shared__ float warpsum[16];
        float ls = 0.f;
        if (valid) {
            float Txe = 0.f, Txo = 0.f, Sxe = 0.f, Sxo = 0.f;
            int widx = (o0 >> 1) + tid;
            #pragma unroll
            for (int q2 = 0; q2 < NSLICE; ++q2) {
                float2 t2 = ((const float2*)(g_pT + q2 * 10240))[widx];
                float2 s2 = ((const float2*)(g_pS + q2 * 10240))[widx];
                Txe += t2.x; Txo += t2.y;
                Sxe += s2.x; Sxo += s2.y;
            }
            float2 pr = *(const float2*)&prob[oe];
            float pxe = (pr.x >= 0.5f) ? 1.0f : 0.0f;
            float pxo = (pr.y >= 0.5f) ? 1.0f : 0.0f;
            ls = fabsf(pxe * Sxe - Txe) + fabsf(pxo * Sxo - Txo);
        }
        #pragma unroll
        for (int off = 16; off; off >>= 1) ls += __shfl_down_sync(0xffffffffu, ls, off);
        if (lane == 0) warpsum[warp] = ls;
        __syncthreads();
        if (tid == 0) {
            float t = 0.f;
            #pragma unroll
            for (int w = 0; w < 16; ++w) t += warpsum[w];
            g_red[chunk] = t;
            __threadfence();
            int old = atomicAdd(&g_ctr2, 1);
            if (old == NCHUNK - 1) {
                float tt = 0.f;
                #pragma unroll
                for (int b = 0; b < NCHUNK; ++b) tt += g_red[b];
                out[0] = tt * (1.0f / ((float)NN * (float)NN));
            }
        }
        __syncthreads();
    }

    // ---------------- replay-safe counter reset ----------------
    __syncthreads();
    if (tid == 0) {
        int fin = atomicAdd(&g_done, 1);
        if (fin == NB - 1) {
            g_barA = 0; g_barB = 0; g_ctr2 = 0; g_done = 0;
            __threadfence();
        }
    }
}

extern "C" void kernel_launch(void* const* d_in, const int* in_sizes, int n_in,
                              void* d_out, int out_size) {
    const float* prob = (const float*)d_in[0];
    const float* gt   = (const float*)d_in[1];
    float* out = (float*)d_out;

    cudaFuncSetAttribute(k_fused, cudaFuncAttributeMaxDynamicSharedMemorySize, SMEM_BYTES);
    k_fused<<<NB, NT, SMEM_BYTES>>>(prob, gt, out);
}